// round 3
// baseline (speedup 1.0000x reference)
#include <cuda_runtime.h>
#include <math.h>

#define NC 20000
#define NV 2000000

__device__ int g_cnt[NC];
__device__ int g_off[NC];
__device__ int g_cur[NC];
__device__ int g_cursor;
__device__ __align__(16) float4 g_sorted[NV];
__device__ float g_acc[10 * NC];          // [c*10 + k], k=0..8 sums (count from g_cnt)
__device__ __align__(16) float4 g_cp[2 * NC]; // [2c]=(cx,cy,cz,_), [2c+1]=(vx,vy,vz,dirwt)

__global__ void k_zero() {
    int i = blockIdx.x * blockDim.x + threadIdx.x;
    if (i < NC) g_cnt[i] = 0;
    if (i == 0) g_cursor = 0;
}

__global__ void k_hist(const int* __restrict__ cl, int n) {
    int i = blockIdx.x * blockDim.x + threadIdx.x;
    if (i < n) atomicAdd(&g_cnt[__ldg(&cl[i])], 1);
}

// Warp-aggregated segment allocation: warp-scan counts, one atomic per warp.
__global__ void k_alloc() {
    int c = blockIdx.x * blockDim.x + threadIdx.x;
    int lane = threadIdx.x & 31;
    unsigned mask = 0xffffffffu;
    int cnt = (c < NC) ? g_cnt[c] : 0;
    // inclusive warp scan
    int v = cnt;
    #pragma unroll
    for (int d = 1; d < 32; d <<= 1) {
        int t = __shfl_up_sync(mask, v, d);
        if (lane >= d) v += t;
    }
    int excl = v - cnt;
    int base = 0;
    if (lane == 31) base = atomicAdd(&g_cursor, v);
    base = __shfl_sync(mask, base, 31);
    if (c < NC) {
        g_off[c] = base + excl;
        g_cur[c] = base + excl;
    }
}

__global__ void k_scatter(const float* __restrict__ data,
                          const int* __restrict__ cl, int n) {
    int i = blockIdx.x * blockDim.x + threadIdx.x;
    if (i >= n) return;
    const float2* d2 = reinterpret_cast<const float2*>(data);
    float2 xy = __ldcs(&d2[3 * i]);
    float2 zw = __ldcs(&d2[3 * i + 1]);
    int c = __ldg(&cl[i]);
    int pos = atomicAdd(&g_cur[c], 1);
    g_sorted[pos] = make_float4(xy.x, xy.y, zw.x, 0.0f);
}

// One warp per cluster: coalesced segment reduction, no atomics.
__global__ void k_accum() {
    int w = blockIdx.x * (blockDim.x >> 5) + (threadIdx.x >> 5);
    if (w >= NC) return;
    int lane = threadIdx.x & 31;
    unsigned mask = 0xffffffffu;
    int off = g_off[w];
    int cnt = g_cnt[w];

    float sx = 0, sy = 0, sz = 0;
    float sxx = 0, sxy = 0, sxz = 0, syy = 0, syz = 0, szz = 0;
    for (int j = lane; j < cnt; j += 32) {
        float4 p = g_sorted[off + j];
        sx += p.x; sy += p.y; sz += p.z;
        sxx += p.x * p.x; sxy += p.x * p.y; sxz += p.x * p.z;
        syy += p.y * p.y; syz += p.y * p.z; szz += p.z * p.z;
    }
    #pragma unroll
    for (int d = 16; d > 0; d >>= 1) {
        sx  += __shfl_xor_sync(mask, sx,  d);
        sy  += __shfl_xor_sync(mask, sy,  d);
        sz  += __shfl_xor_sync(mask, sz,  d);
        sxx += __shfl_xor_sync(mask, sxx, d);
        sxy += __shfl_xor_sync(mask, sxy, d);
        sxz += __shfl_xor_sync(mask, sxz, d);
        syy += __shfl_xor_sync(mask, syy, d);
        syz += __shfl_xor_sync(mask, syz, d);
        szz += __shfl_xor_sync(mask, szz, d);
    }
    if (lane == 0) {
        float* b = &g_acc[w * 10];
        b[0] = sx;  b[1] = sy;  b[2] = sz;
        b[3] = sxx; b[4] = sxy; b[5] = sxz;
        b[6] = syy; b[7] = syz; b[8] = szz;
    }
}

__global__ void k_eig(float* __restrict__ out) {
    int c = blockIdx.x * blockDim.x + threadIdx.x;
    if (c >= NC) return;
    const float* b = &g_acc[c * 10];

    double n  = (double)g_cnt[c];
    double Sx = (double)b[0], Sy = (double)b[1], Sz = (double)b[2];
    double inv = 1.0 / n;
    double cx = Sx * inv, cy = Sy * inv, cz = Sz * inv;

    double a00 = (double)b[3] - Sx * cx;
    double a01 = (double)b[4] - Sx * cy;
    double a02 = (double)b[5] - Sx * cz;
    double a11 = (double)b[6] - Sy * cy;
    double a12 = (double)b[7] - Sy * cz;
    double a22 = (double)b[8] - Sz * cz;

    double q = (a00 + a11 + a22) / 3.0;
    double b00 = a00 - q, b11 = a11 - q, b22 = a22 - q;
    double p2 = b00 * b00 + b11 * b11 + b22 * b22
              + 2.0 * (a01 * a01 + a02 * a02 + a12 * a12);
    double p = sqrt(p2 / 6.0);

    double e1 = q, e2 = q;
    double vx = 1.0, vy = 0.0, vz = 0.0;

    if (p > 0.0) {
        double ip = 1.0 / p;
        double c00 = b00 * ip, c11 = b11 * ip, c22 = b22 * ip;
        double c01 = a01 * ip, c02 = a02 * ip, c12 = a12 * ip;
        double r = 0.5 * (c00 * (c11 * c22 - c12 * c12)
                        - c01 * (c01 * c22 - c12 * c02)
                        + c02 * (c01 * c12 - c11 * c02));
        r = fmin(1.0, fmax(-1.0, r));
        double phi = acos(r) / 3.0;
        e1 = q + 2.0 * p * cos(phi);
        double e3 = q + 2.0 * p * cos(phi + 2.0943951023931953);
        e2 = 3.0 * q - e1 - e3;

        double p00 = a00 - e2, p11 = a11 - e2, p22 = a22 - e2;
        double q00 = a00 - e3, q11 = a11 - e3, q22 = a22 - e3;

        double m0x = p00 * q00 + a01 * a01 + a02 * a02;
        double m0y = a01 * q00 + p11 * a01 + a12 * a02;
        double m0z = a02 * q00 + a12 * a01 + p22 * a02;
        double m1x = p00 * a01 + a01 * q11 + a02 * a12;
        double m1y = a01 * a01 + p11 * q11 + a12 * a12;
        double m1z = a02 * a01 + a12 * q11 + p22 * a12;
        double m2x = p00 * a02 + a01 * a12 + a02 * q22;
        double m2y = a01 * a02 + p11 * a12 + a12 * q22;
        double m2z = a02 * a02 + a12 * a12 + p22 * q22;

        double n0 = m0x * m0x + m0y * m0y + m0z * m0z;
        double n1 = m1x * m1x + m1y * m1y + m1z * m1z;
        double n2 = m2x * m2x + m2y * m2y + m2z * m2z;

        if (n0 >= n1 && n0 >= n2) { vx = m0x; vy = m0y; vz = m0z; }
        else if (n1 >= n2)        { vx = m1x; vy = m1y; vz = m1z; }
        else                      { vx = m2x; vy = m2y; vz = m2z; }

        double nv = vx * vx + vy * vy + vz * vz;
        if (nv > 0.0) {
            double s = 1.0 / sqrt(nv);
            vx *= s; vy *= s; vz *= s;
        } else { vx = 1.0; vy = 0.0; vz = 0.0; }
    }

    float* o = out + (size_t)c * 16;
    o[0] = (float)cx; o[1] = (float)cy; o[2] = (float)cz;
    double iw = 1.0 / e1;
    o[3]  = (float)(a00 * iw); o[4]  = (float)(a01 * iw); o[5]  = (float)(a02 * iw);
    o[6]  = (float)(a01 * iw); o[7]  = (float)(a11 * iw); o[8]  = (float)(a12 * iw);
    o[9]  = (float)(a02 * iw); o[10] = (float)(a12 * iw); o[11] = (float)(a22 * iw);
    o[15] = (float)n;

    g_cp[2 * c]     = make_float4((float)cx, (float)cy, (float)cz, 0.0f);
    g_cp[2 * c + 1] = make_float4((float)vx, (float)vy, (float)vz,
                                  (float)(1.0 - e2 / e1));
}

// One warp per cluster: sc reduction over sorted segment + final v0 write.
__global__ void k_sc(float* __restrict__ out) {
    int w = blockIdx.x * (blockDim.x >> 5) + (threadIdx.x >> 5);
    if (w >= NC) return;
    int lane = threadIdx.x & 31;
    unsigned mask = 0xffffffffu;
    int off = g_off[w];
    int cnt = g_cnt[w];
    float4 cen = g_cp[2 * w];
    float4 v   = g_cp[2 * w + 1];

    float sc = 0.0f;
    for (int j = lane; j < cnt; j += 32) {
        float4 p = g_sorted[off + j];
        float xc = p.x - cen.x;
        float yc = p.y - cen.y;
        float zc = p.z - cen.z;
        float x0 = xc * v.x + yc * v.y + zc * v.z;
        float px = xc - x0 * v.x;
        float py = yc - x0 * v.y;
        float pz = zc - x0 * v.z;
        sc += x0 * sqrtf(px * px + py * py + pz * pz);
    }
    #pragma unroll
    for (int d = 16; d > 0; d >>= 1)
        sc += __shfl_xor_sync(mask, sc, d);

    if (lane == 0) {
        float f = (sc < 0.0f) ? -v.w : v.w;
        float* o = out + (size_t)w * 16;
        o[12] = v.x * f;
        o[13] = v.y * f;
        o[14] = v.z * f;
    }
}

extern "C" void kernel_launch(void* const* d_in, const int* in_sizes, int n_in,
                              void* d_out, int out_size) {
    const float* data = (const float*)d_in[0];
    const int* cl = (const int*)d_in[1];
    float* out = (float*)d_out;
    int n = in_sizes[1];

    k_zero<<<(NC + 255) / 256, 256>>>();
    k_hist<<<(n + 255) / 256, 256>>>(cl, n);
    k_alloc<<<(NC + 255) / 256, 256>>>();
    k_scatter<<<(n + 255) / 256, 256>>>(data, cl, n);
    k_accum<<<(NC * 32 + 255) / 256, 256>>>();
    k_eig<<<(NC + 255) / 256, 256>>>(out);
    k_sc<<<(NC * 32 + 255) / 256, 256>>>(out);
}